// round 6
// baseline (speedup 1.0000x reference)
#include <cuda_runtime.h>
#include <cuda_bf16.h>
#include <cstdint>

#define NN 8192
#define IND 512
#define DD 64
#define ALPHA 0.2f

#define JS 4
#define JLEN (NN/JS)      // 2048
#define KT 64             // j per tile
#define NTILES (JLEN/KT)  // 32

// -------- device scratch --------
__device__ __align__(16) float g_h1[NN];
__device__ __align__(16) float g_h2[NN];
__device__ __align__(16) __nv_bfloat16 g_ht_hi[(size_t)DD*NN];
__device__ __align__(16) __nv_bfloat16 g_ht_lo[(size_t)DD*NN];
__device__ __align__(16) float g_acc[(size_t)JS*NN*DD];
__device__ __align__(16) float g_Z[JS*NN];

// -------- helpers --------
__device__ __forceinline__ uint32_t s2u(const void* p) {
    uint32_t a;
    asm("{ .reg .u64 t; cvta.to.shared.u64 t, %1; cvt.u32.u64 %0, t; }" : "=r"(a) : "l"(p));
    return a;
}
#define CPA16(dst, src) asm volatile("cp.async.cg.shared.global [%0], [%1], 16;" :: "r"(dst), "l"(src))
#define CPCOMMIT()      asm volatile("cp.async.commit_group;" ::: "memory")
#define CPWAIT0()       asm volatile("cp.async.wait_group 0;" ::: "memory")
#define CPWAIT1()       asm volatile("cp.async.wait_group 1;" ::: "memory")
#define LDM4(r, a) \
    asm volatile("ldmatrix.sync.aligned.m8n8.x4.shared.b16 {%0,%1,%2,%3},[%4];" \
        : "=r"((r)[0]), "=r"((r)[1]), "=r"((r)[2]), "=r"((r)[3]) : "r"(a))
#define MMA(d, a, b0, b1) \
    asm volatile("mma.sync.aligned.m16n8k16.row.col.f32.bf16.bf16.f32 " \
        "{%0,%1,%2,%3},{%4,%5,%6,%7},{%8,%9},{%0,%1,%2,%3};" \
        : "+f"((d)[0]), "+f"((d)[1]), "+f"((d)[2]), "+f"((d)[3]) \
        : "r"((a)[0]), "r"((a)[1]), "r"((a)[2]), "r"((a)[3]), "r"(b0), "r"(b1))

// ---------------- kernel 1: fused  h=X@W -> ht_hi/lo (transposed), h1, h2 ----------------
// 128 CTAs x 64 rows. c = tid&63, 16 rows per thread. FFMA-bound inner loop.
__global__ void __launch_bounds__(256) gemm_fused_kernel(const float* __restrict__ X,
                                                         const float* __restrict__ W,
                                                         const float* __restrict__ av) {
    __shared__ float sbuf[64 * 128];      // 32 KB: X k-tile; reused as hs[64][65] after compute
    const int tid = threadIdx.x;
    const int row0 = blockIdx.x * 64;
    const int c  = tid & 63;
    const int rg = tid >> 6;

    const uint32_t sb = s2u(sbuf);
    float acc[16];
    #pragma unroll
    for (int r = 0; r < 16; r++) acc[r] = 0.f;

    for (int kt = 0; kt < 4; kt++) {
        // stage X[row0..row0+63][kt*128 .. +128] -> sbuf[row][k]
        #pragma unroll
        for (int q = 0; q < 8; q++) {
            const int idx = tid + q * 256;          // 0..2047
            const int row = idx >> 5, f4 = idx & 31;
            CPA16(sb + (uint32_t)(row * 128 + f4 * 4) * 4,
                  X + (size_t)(row0 + row) * IND + kt * 128 + f4 * 4);
        }
        CPCOMMIT();
        CPWAIT0();
        __syncthreads();

        const float* wp = W + (size_t)(kt * 128) * DD + c;
        #pragma unroll 2
        for (int k4 = 0; k4 < 32; k4++) {
            const float w0 = wp[(k4*4 + 0) * DD];
            const float w1 = wp[(k4*4 + 1) * DD];
            const float w2 = wp[(k4*4 + 2) * DD];
            const float w3 = wp[(k4*4 + 3) * DD];
            #pragma unroll
            for (int r = 0; r < 16; r++) {
                const float4 x = *(const float4*)(sbuf + (rg*16 + r) * 128 + k4 * 4);
                acc[r] = fmaf(x.x, w0, acc[r]);
                acc[r] = fmaf(x.y, w1, acc[r]);
                acc[r] = fmaf(x.z, w2, acc[r]);
                acc[r] = fmaf(x.w, w3, acc[r]);
            }
        }
        __syncthreads();   // before next stage overwrites sbuf
    }

    // dump accumulators to transpose buffer hs[row][c] (stride 65, conflict-free)
    #pragma unroll
    for (int r = 0; r < 16; r++) sbuf[(rg*16 + r) * 65 + c] = acc[r];
    __syncthreads();

    const int wd = tid >> 5, lane = tid & 31;

    // ht hi/lo planes: for fixed c, rows contiguous -> 64B coalesced stores
    #pragma unroll
    for (int cc = 0; cc < 8; cc++) {
        const int c2 = wd * 8 + cc;
        #pragma unroll
        for (int rr = 0; rr < 2; rr++) {
            const int row = rr * 32 + lane;
            const float v = sbuf[row * 65 + c2];
            const __nv_bfloat16 hb = __float2bfloat16(v);
            const __nv_bfloat16 lb = __float2bfloat16(v - __bfloat162float(hb));
            g_ht_hi[(size_t)c2 * NN + row0 + row] = hb;
            g_ht_lo[(size_t)c2 * NN + row0 + row] = lb;
        }
    }

    // projections h1/h2: warp wd handles rows wd*8..wd*8+7
    const float a1 = av[lane], a1b = av[lane + 32];
    const float a2 = av[64 + lane], a2b = av[96 + lane];
    #pragma unroll
    for (int rr = 0; rr < 8; rr++) {
        const int row = wd * 8 + rr;
        const float x0 = sbuf[row * 65 + lane];
        const float x1 = sbuf[row * 65 + lane + 32];
        float s1 = x0 * a1 + x1 * a1b;
        float s2 = x0 * a2 + x1 * a2b;
        #pragma unroll
        for (int o = 16; o > 0; o >>= 1) {
            s1 += __shfl_xor_sync(0xffffffffu, s1, o);
            s2 += __shfl_xor_sync(0xffffffffu, s2, o);
        }
        if (lane == 0) { g_h1[row0 + row] = s1; g_h2[row0 + row] = s2; }
    }
}

// ---------------- kernel 2: fused attention ----------------
__device__ __forceinline__ float pexp(int a, float e) {
    const float s = fmaxf(e, ALPHA * e);
    const float p = __expf(s);
    return (a > 0) ? p : 0.f;
}
__device__ __forceinline__ uint32_t pack_hilo(float x, float y, uint32_t& lo) {
    __nv_bfloat162 H = __float22bfloat162_rn(make_float2(x, y));
    float2 f = __bfloat1622float2(H);
    __nv_bfloat162 L = __float22bfloat162_rn(make_float2(x - f.x, y - f.y));
    lo = *reinterpret_cast<uint32_t*>(&L);
    return *reinterpret_cast<uint32_t*>(&H);
}

// 128 threads (4 warps), 64 rows per CTA. grid (JS, NN/64). 3 CTAs/SM.
__global__ void __launch_bounds__(128, 3) attn_kernel(const int* __restrict__ adj) {
    // [buf][hi/lo][c][j], 128B rows, XOR(seg^row) swizzle -> conflict-free
    __shared__ __nv_bfloat16 hts[2][2][64][64];   // 32 KB

    const int tid = threadIdx.x, lane = tid & 31, w = tid >> 5;
    const int jsb = blockIdx.x;
    const int row0 = blockIdx.y * 64;
    const int jbase = jsb * JLEN;
    const int g  = row0 + w * 16 + (lane >> 2);   // A-frag rows g, g+8
    const int jq = (lane & 3) * 2;

    const float h1a = g_h1[g];
    const float h1b = g_h1[g + 8];
    const int* adjA = adj + (size_t)g * NN;
    const int* adjB = adj + (size_t)(g + 8) * NN;

    const int lmr = lane & 7;
    const uint32_t smem0 = s2u(&hts[0][0][0][0]);
    const uint32_t PL   = 64 * 64 * 2;            // plane stride (bytes)
    const uint32_t BUFB = 2 * PL;

    uint32_t cdst[4];
    const __nv_bfloat16* csrc_h[4];
    const __nv_bfloat16* csrc_l[4];
    #pragma unroll
    for (int q = 0; q < 4; q++) {
        const int idx = tid + q * 128;            // 0..511
        const int c = idx >> 3, seg = idx & 7;
        const int phys = seg ^ (c & 7);
        cdst[q] = smem0 + (uint32_t)(c * 64 + phys * 8) * 2;
        csrc_h[q] = g_ht_hi + (size_t)c * NN + seg * 8;
        csrc_l[q] = g_ht_lo + (size_t)c * NN + seg * 8;
    }

    float acc[8][4];
    #pragma unroll
    for (int nb = 0; nb < 8; nb++) { acc[nb][0]=acc[nb][1]=acc[nb][2]=acc[nb][3]=0.f; }
    float z0 = 0.f, z1 = 0.f;

    // ---- prologue: prefetch adj/h2 for tile 0, stage H tile 0 ----
    int2 pa[4][4];
    float2 ph0[4], ph1[4];
    #pragma unroll
    for (int kb = 0; kb < 4; kb++) {
        const int jb = jbase + kb * 16 + jq;
        pa[kb][0] = __ldcs((const int2*)(adjA + jb));
        pa[kb][1] = __ldcs((const int2*)(adjB + jb));
        pa[kb][2] = __ldcs((const int2*)(adjA + jb + 8));
        pa[kb][3] = __ldcs((const int2*)(adjB + jb + 8));
        ph0[kb] = *(const float2*)(g_h2 + jb);
        ph1[kb] = *(const float2*)(g_h2 + jb + 8);
    }
    #pragma unroll
    for (int q = 0; q < 4; q++) {
        CPA16(cdst[q],      csrc_h[q] + jbase);
        CPA16(cdst[q] + PL, csrc_l[q] + jbase);
    }
    CPCOMMIT();

    for (int t = 0; t < NTILES; t++) {
        const uint32_t curb = smem0 + (uint32_t)(t & 1) * BUFB;

        // ---- P fragments from prefetched adj/h2 ----
        uint32_t ahi[4][4], alo[4][4];
        #pragma unroll
        for (int kb = 0; kb < 4; kb++) {
            const float p00 = pexp(pa[kb][0].x, h1a + ph0[kb].x), p01 = pexp(pa[kb][0].y, h1a + ph0[kb].y);
            const float p10 = pexp(pa[kb][1].x, h1b + ph0[kb].x), p11 = pexp(pa[kb][1].y, h1b + ph0[kb].y);
            const float p02 = pexp(pa[kb][2].x, h1a + ph1[kb].x), p03 = pexp(pa[kb][2].y, h1a + ph1[kb].y);
            const float p12 = pexp(pa[kb][3].x, h1b + ph1[kb].x), p13 = pexp(pa[kb][3].y, h1b + ph1[kb].y);
            z0 += (p00 + p01) + (p02 + p03);
            z1 += (p10 + p11) + (p12 + p13);
            ahi[kb][0] = pack_hilo(p00, p01, alo[kb][0]);
            ahi[kb][1] = pack_hilo(p10, p11, alo[kb][1]);
            ahi[kb][2] = pack_hilo(p02, p03, alo[kb][2]);
            ahi[kb][3] = pack_hilo(p12, p13, alo[kb][3]);
        }

        // ---- prefetch next tile's adj/h2 (hidden under MMA phase) ----
        const int jn = (t + 1 < NTILES) ? jbase + (t + 1) * KT : jbase;
        #pragma unroll
        for (int kb = 0; kb < 4; kb++) {
            const int jb = jn + kb * 16 + jq;
            pa[kb][0] = __ldcs((const int2*)(adjA + jb));
            pa[kb][1] = __ldcs((const int2*)(adjB + jb));
            pa[kb][2] = __ldcs((const int2*)(adjA + jb + 8));
            pa[kb][3] = __ldcs((const int2*)(adjB + jb + 8));
            ph0[kb] = *(const float2*)(g_h2 + jb);
            ph1[kb] = *(const float2*)(g_h2 + jb + 8);
        }

        // ---- stage next H tile ----
        if (t + 1 < NTILES) {
            const uint32_t nxtb = (uint32_t)((t + 1) & 1) * BUFB;
            #pragma unroll
            for (int q = 0; q < 4; q++) {
                CPA16(cdst[q] + nxtb,      csrc_h[q] + jn);
                CPA16(cdst[q] + nxtb + PL, csrc_l[q] + jn);
            }
        }
        CPCOMMIT();
        CPWAIT1();
        __syncthreads();

        // ---- MMAs with ldmatrix B loads ----
        #pragma unroll
        for (int nb = 0; nb < 8; nb++) {
            const int rowc = nb * 8 + lmr;
            const uint32_t rowa = curb +
                (uint32_t)(rowc * 64 + (((lane >> 3) ^ lmr) * 8)) * 2;
            uint32_t bh[8], bl[8];
            LDM4(bh,     rowa);             // j 0..31
            LDM4(bh + 4, rowa ^ 64u);       // j 32..63
            LDM4(bl,     rowa + PL);
            LDM4(bl + 4, (rowa + PL) ^ 64u);
            #pragma unroll
            for (int kb = 0; kb < 4; kb++) {
                MMA(acc[nb], ahi[kb], bh[2*kb], bh[2*kb+1]);
                MMA(acc[nb], alo[kb], bh[2*kb], bh[2*kb+1]);
                MMA(acc[nb], ahi[kb], bl[2*kb], bl[2*kb+1]);
            }
        }
        __syncthreads();
    }

    // ---- Z reduce across 4 lanes sharing a row ----
    z0 += __shfl_xor_sync(0xffffffffu, z0, 1);
    z0 += __shfl_xor_sync(0xffffffffu, z0, 2);
    z1 += __shfl_xor_sync(0xffffffffu, z1, 1);
    z1 += __shfl_xor_sync(0xffffffffu, z1, 2);
    if ((lane & 3) == 0) {
        g_Z[jsb*NN + g]     = z0;
        g_Z[jsb*NN + g + 8] = z1;
    }

    // ---- partial numerators ----
    #pragma unroll
    for (int nb = 0; nb < 8; nb++) {
        float2 v0; v0.x = acc[nb][0]; v0.y = acc[nb][1];
        float2 v1; v1.x = acc[nb][2]; v1.y = acc[nb][3];
        *(float2*)&g_acc[((size_t)jsb*NN + g    )*DD + nb*8 + jq] = v0;
        *(float2*)&g_acc[((size_t)jsb*NN + g + 8)*DD + nb*8 + jq] = v1;
    }
}

// ---------------- kernel 3: combine splits, normalize, ELU ----------------
__global__ void __launch_bounds__(256) combine_kernel(float* __restrict__ out) {
    const int gid = blockIdx.x * 256 + threadIdx.x;
    const int i = gid >> 6;
    float s = 0.f, z = 0.f;
    #pragma unroll
    for (int q = 0; q < JS; q++) {
        s += g_acc[(size_t)q*NN*DD + gid];
        z += g_Z[q*NN + i];
    }
    const float o = s / z;
    out[gid] = (o > 0.f) ? o : expm1f(o);
}

// ---------------- launcher ----------------
extern "C" void kernel_launch(void* const* d_in, const int* in_sizes, int n_in,
                              void* d_out, int out_size) {
    const float* features = (const float*)d_in[0];
    const int*   adj      = (const int*)d_in[1];
    const float* W        = (const float*)d_in[2];
    const float* a        = (const float*)d_in[3];
    float* out = (float*)d_out;

    gemm_fused_kernel<<<NN/64, 256>>>(features, W, a);
    attn_kernel<<<dim3(JS, NN/64), 128>>>(adj);
    combine_kernel<<<(NN*DD)/256, 256>>>(out);
}

// round 7
// speedup vs baseline: 1.2210x; 1.2210x over previous
#include <cuda_runtime.h>
#include <cuda_bf16.h>
#include <cstdint>

#define NN 8192
#define IND 512
#define DD 64
#define ALPHA 0.2f

#define JS 4
#define JLEN (NN/JS)      // 2048
#define KT 64             // j per tile
#define NTILES (JLEN/KT)  // 32

// -------- device scratch --------
__device__ __align__(16) float g_h[NN*DD];
__device__ __align__(16) float g_h1[NN];
__device__ __align__(16) float g_h2[NN];
__device__ __align__(16) __nv_bfloat16 g_ht_hi[(size_t)DD*NN];
__device__ __align__(16) __nv_bfloat16 g_ht_lo[(size_t)DD*NN];
__device__ __align__(16) float g_acc[(size_t)JS*NN*DD];
__device__ __align__(16) float g_Z[JS*NN];

// -------- helpers --------
__device__ __forceinline__ uint32_t s2u(const void* p) {
    uint32_t a;
    asm("{ .reg .u64 t; cvta.to.shared.u64 t, %1; cvt.u32.u64 %0, t; }" : "=r"(a) : "l"(p));
    return a;
}
#define CPA16(dst, src) asm volatile("cp.async.cg.shared.global [%0], [%1], 16;" :: "r"(dst), "l"(src))
#define CPCOMMIT()      asm volatile("cp.async.commit_group;" ::: "memory")
#define CPWAIT1()       asm volatile("cp.async.wait_group 1;" ::: "memory")
#define LDM4(r, a) \
    asm volatile("ldmatrix.sync.aligned.m8n8.x4.shared.b16 {%0,%1,%2,%3},[%4];" \
        : "=r"((r)[0]), "=r"((r)[1]), "=r"((r)[2]), "=r"((r)[3]) : "r"(a))
#define MMA(d, a, b0, b1) \
    asm volatile("mma.sync.aligned.m16n8k16.row.col.f32.bf16.bf16.f32 " \
        "{%0,%1,%2,%3},{%4,%5,%6,%7},{%8,%9},{%0,%1,%2,%3};" \
        : "+f"((d)[0]), "+f"((d)[1]), "+f"((d)[2]), "+f"((d)[3]) \
        : "r"((a)[0]), "r"((a)[1]), "r"((a)[2]), "r"((a)[3]), "r"(b0), "r"(b1))

// ---------------- kernel 1: h = X @ W  (measured-best variant) ----------------
__global__ void __launch_bounds__(256) gemm_h_kernel(const float* __restrict__ X,
                                                     const float* __restrict__ W) {
    __shared__ float xs[16][IND];
    const int tid = threadIdx.x;
    const int row0 = blockIdx.x * 16;
    {
        const float4* src = (const float4*)(X + (size_t)row0 * IND);
        float4* dst = (float4*)&xs[0][0];
        #pragma unroll
        for (int i = 0; i < 8; i++) dst[tid + i*256] = src[tid + i*256];
    }
    __syncthreads();
    const int c  = tid & 63;
    const int rg = tid >> 6;
    float a0 = 0.f, a1 = 0.f, a2 = 0.f, a3 = 0.f;
    #pragma unroll 4
    for (int k = 0; k < IND; k++) {
        const float w = W[k*DD + c];
        a0 += xs[rg*4+0][k] * w;
        a1 += xs[rg*4+1][k] * w;
        a2 += xs[rg*4+2][k] * w;
        a3 += xs[rg*4+3][k] * w;
    }
    g_h[(row0 + rg*4+0)*DD + c] = a0;
    g_h[(row0 + rg*4+1)*DD + c] = a1;
    g_h[(row0 + rg*4+2)*DD + c] = a2;
    g_h[(row0 + rg*4+3)*DD + c] = a3;
}

// ---------------- kernel 2: transpose h -> ht_hi/ht_lo (bf16 split) ----------------
__global__ void __launch_bounds__(256) ht_kernel() {
    __shared__ float ts[64][65];
    const int tid = threadIdx.x;
    const int j0 = blockIdx.x * 64;
    #pragma unroll
    for (int k = 0; k < 16; ++k) {
        int e = k*256 + tid;
        ts[e>>6][e&63] = g_h[(j0 + (e>>6))*DD + (e&63)];
    }
    __syncthreads();
    #pragma unroll
    for (int k = 0; k < 16; ++k) {
        int e = k*256 + tid;
        int c = e >> 6, jj = e & 63;
        float v = ts[jj][c];
        __nv_bfloat16 hb = __float2bfloat16(v);
        g_ht_hi[(size_t)c*NN + j0 + jj] = hb;
        g_ht_lo[(size_t)c*NN + j0 + jj] = __float2bfloat16(v - __bfloat162float(hb));
    }
}

// ---------------- kernel 3: h1 / h2 projections ----------------
__global__ void __launch_bounds__(256) proj_kernel(const float* __restrict__ a) {
    const int w = threadIdx.x >> 5, lane = threadIdx.x & 31;
    const int row = blockIdx.x * 8 + w;
    const float x0 = g_h[row*DD + lane];
    const float x1 = g_h[row*DD + 32 + lane];
    float s1 = x0 * a[lane]      + x1 * a[lane + 32];
    float s2 = x0 * a[64 + lane] + x1 * a[96 + lane];
    #pragma unroll
    for (int o = 16; o > 0; o >>= 1) {
        s1 += __shfl_xor_sync(0xffffffffu, s1, o);
        s2 += __shfl_xor_sync(0xffffffffu, s2, o);
    }
    if (lane == 0) { g_h1[row] = s1; g_h2[row] = s2; }
}

// ---------------- kernel 4: fused attention (measured-best config) ----------------
__device__ __forceinline__ float pexp(int a, float e) {
    const float s = fmaxf(e, ALPHA * e);
    const float p = __expf(s);
    return (a > 0) ? p : 0.f;
}
__device__ __forceinline__ uint32_t pack_hilo(float x, float y, uint32_t& lo) {
    __nv_bfloat162 H = __float22bfloat162_rn(make_float2(x, y));
    float2 f = __bfloat1622float2(H);
    __nv_bfloat162 L = __float22bfloat162_rn(make_float2(x - f.x, y - f.y));
    lo = *reinterpret_cast<uint32_t*>(&L);
    return *reinterpret_cast<uint32_t*>(&H);
}

// 128 threads (4 warps), 64 rows per CTA. grid (JS, NN/64). 2 CTAs/SM.
__global__ void __launch_bounds__(128, 2) attn_kernel(const int* __restrict__ adj) {
    // [buf][hi/lo][c][j], 128B rows, XOR(seg^row) swizzle -> conflict-free
    __shared__ __nv_bfloat16 hts[2][2][64][64];   // 32 KB

    const int tid = threadIdx.x, lane = tid & 31, w = tid >> 5;
    const int jsb = blockIdx.x;
    const int row0 = blockIdx.y * 64;
    const int jbase = jsb * JLEN;
    const int g  = row0 + w * 16 + (lane >> 2);   // A-frag rows g, g+8
    const int jq = (lane & 3) * 2;

    const float h1a = g_h1[g];
    const float h1b = g_h1[g + 8];
    const int* adjA = adj + (size_t)g * NN;
    const int* adjB = adj + (size_t)(g + 8) * NN;

    const int lmr = lane & 7;
    const uint32_t smem0 = s2u(&hts[0][0][0][0]);
    const uint32_t PL   = 64 * 64 * 2;            // plane stride (bytes)
    const uint32_t BUFB = 2 * PL;

    uint32_t cdst[4];
    const __nv_bfloat16* csrc_h[4];
    const __nv_bfloat16* csrc_l[4];
    #pragma unroll
    for (int q = 0; q < 4; q++) {
        const int idx = tid + q * 128;            // 0..511
        const int c = idx >> 3, seg = idx & 7;
        const int phys = seg ^ (c & 7);
        cdst[q] = smem0 + (uint32_t)(c * 64 + phys * 8) * 2;
        csrc_h[q] = g_ht_hi + (size_t)c * NN + seg * 8;
        csrc_l[q] = g_ht_lo + (size_t)c * NN + seg * 8;
    }

    float acc[8][4];
    #pragma unroll
    for (int nb = 0; nb < 8; nb++) { acc[nb][0]=acc[nb][1]=acc[nb][2]=acc[nb][3]=0.f; }
    float z0 = 0.f, z1 = 0.f;

    // ---- prologue: prefetch adj/h2 for tile 0, stage H tile 0 ----
    int2 pa[4][4];
    float2 ph0[4], ph1[4];
    #pragma unroll
    for (int kb = 0; kb < 4; kb++) {
        const int jb = jbase + kb * 16 + jq;
        pa[kb][0] = __ldcs((const int2*)(adjA + jb));
        pa[kb][1] = __ldcs((const int2*)(adjB + jb));
        pa[kb][2] = __ldcs((const int2*)(adjA + jb + 8));
        pa[kb][3] = __ldcs((const int2*)(adjB + jb + 8));
        ph0[kb] = *(const float2*)(g_h2 + jb);
        ph1[kb] = *(const float2*)(g_h2 + jb + 8);
    }
    #pragma unroll
    for (int q = 0; q < 4; q++) {
        CPA16(cdst[q],      csrc_h[q] + jbase);
        CPA16(cdst[q] + PL, csrc_l[q] + jbase);
    }
    CPCOMMIT();

    for (int t = 0; t < NTILES; t++) {
        const uint32_t curb = smem0 + (uint32_t)(t & 1) * BUFB;

        // ---- P fragments from prefetched adj/h2 ----
        uint32_t ahi[4][4], alo[4][4];
        #pragma unroll
        for (int kb = 0; kb < 4; kb++) {
            const float p00 = pexp(pa[kb][0].x, h1a + ph0[kb].x), p01 = pexp(pa[kb][0].y, h1a + ph0[kb].y);
            const float p10 = pexp(pa[kb][1].x, h1b + ph0[kb].x), p11 = pexp(pa[kb][1].y, h1b + ph0[kb].y);
            const float p02 = pexp(pa[kb][2].x, h1a + ph1[kb].x), p03 = pexp(pa[kb][2].y, h1a + ph1[kb].y);
            const float p12 = pexp(pa[kb][3].x, h1b + ph1[kb].x), p13 = pexp(pa[kb][3].y, h1b + ph1[kb].y);
            z0 += (p00 + p01) + (p02 + p03);
            z1 += (p10 + p11) + (p12 + p13);
            ahi[kb][0] = pack_hilo(p00, p01, alo[kb][0]);
            ahi[kb][1] = pack_hilo(p10, p11, alo[kb][1]);
            ahi[kb][2] = pack_hilo(p02, p03, alo[kb][2]);
            ahi[kb][3] = pack_hilo(p12, p13, alo[kb][3]);
        }

        // ---- prefetch next tile's adj/h2 (hidden under MMA phase) ----
        const int jn = (t + 1 < NTILES) ? jbase + (t + 1) * KT : jbase;
        #pragma unroll
        for (int kb = 0; kb < 4; kb++) {
            const int jb = jn + kb * 16 + jq;
            pa[kb][0] = __ldcs((const int2*)(adjA + jb));
            pa[kb][1] = __ldcs((const int2*)(adjB + jb));
            pa[kb][2] = __ldcs((const int2*)(adjA + jb + 8));
            pa[kb][3] = __ldcs((const int2*)(adjB + jb + 8));
            ph0[kb] = *(const float2*)(g_h2 + jb);
            ph1[kb] = *(const float2*)(g_h2 + jb + 8);
        }

        // ---- stage next H tile ----
        if (t + 1 < NTILES) {
            const uint32_t nxtb = (uint32_t)((t + 1) & 1) * BUFB;
            #pragma unroll
            for (int q = 0; q < 4; q++) {
                CPA16(cdst[q] + nxtb,      csrc_h[q] + jn);
                CPA16(cdst[q] + nxtb + PL, csrc_l[q] + jn);
            }
        }
        CPCOMMIT();
        CPWAIT1();
        __syncthreads();

        // ---- MMAs with ldmatrix B loads ----
        #pragma unroll
        for (int nb = 0; nb < 8; nb++) {
            const int rowc = nb * 8 + lmr;
            const uint32_t rowa = curb +
                (uint32_t)(rowc * 64 + (((lane >> 3) ^ lmr) * 8)) * 2;
            uint32_t bh[8], bl[8];
            LDM4(bh,     rowa);             // j 0..31
            LDM4(bh + 4, rowa ^ 64u);       // j 32..63
            LDM4(bl,     rowa + PL);
            LDM4(bl + 4, (rowa + PL) ^ 64u);
            #pragma unroll
            for (int kb = 0; kb < 4; kb++) {
                MMA(acc[nb], ahi[kb], bh[2*kb], bh[2*kb+1]);
                MMA(acc[nb], alo[kb], bh[2*kb], bh[2*kb+1]);
                MMA(acc[nb], ahi[kb], bl[2*kb], bl[2*kb+1]);
            }
        }
        __syncthreads();
    }

    // ---- Z reduce across 4 lanes sharing a row ----
    z0 += __shfl_xor_sync(0xffffffffu, z0, 1);
    z0 += __shfl_xor_sync(0xffffffffu, z0, 2);
    z1 += __shfl_xor_sync(0xffffffffu, z1, 1);
    z1 += __shfl_xor_sync(0xffffffffu, z1, 2);
    if ((lane & 3) == 0) {
        g_Z[jsb*NN + g]     = z0;
        g_Z[jsb*NN + g + 8] = z1;
    }

    // ---- partial numerators ----
    #pragma unroll
    for (int nb = 0; nb < 8; nb++) {
        float2 v0; v0.x = acc[nb][0]; v0.y = acc[nb][1];
        float2 v1; v1.x = acc[nb][2]; v1.y = acc[nb][3];
        *(float2*)&g_acc[((size_t)jsb*NN + g    )*DD + nb*8 + jq] = v0;
        *(float2*)&g_acc[((size_t)jsb*NN + g + 8)*DD + nb*8 + jq] = v1;
    }
}

// ---------------- kernel 5: combine splits, normalize, ELU ----------------
__global__ void __launch_bounds__(256) combine_kernel(float* __restrict__ out) {
    const int gid = blockIdx.x * 256 + threadIdx.x;
    const int i = gid >> 6;
    float s = 0.f, z = 0.f;
    #pragma unroll
    for (int q = 0; q < JS; q++) {
        s += g_acc[(size_t)q*NN*DD + gid];
        z += g_Z[q*NN + i];
    }
    const float o = s / z;
    out[gid] = (o > 0.f) ? o : expm1f(o);
}

// ---------------- launcher ----------------
extern "C" void kernel_launch(void* const* d_in, const int* in_sizes, int n_in,
                              void* d_out, int out_size) {
    const float* features = (const float*)d_in[0];
    const int*   adj      = (const int*)d_in[1];
    const float* W        = (const float*)d_in[2];
    const float* a        = (const float*)d_in[3];
    float* out = (float*)d_out;

    gemm_h_kernel<<<NN/16, 256>>>(features, W);
    ht_kernel<<<NN/64, 256>>>();
    proj_kernel<<<NN/8, 256>>>(a);
    attn_kernel<<<dim3(JS, NN/64), 128>>>(adj);
    combine_kernel<<<(NN*DD)/256, 256>>>(out);
}

// round 9
// speedup vs baseline: 1.3501x; 1.1057x over previous
#include <cuda_runtime.h>
#include <cuda_bf16.h>
#include <cstdint>

#define NN 8192
#define IND 512
#define DD 64
#define ALPHA 0.2f

#define JS 4
#define JLEN (NN/JS)      // 2048
#define KT 64             // j per tile
#define NTILES (JLEN/KT)  // 32

// -------- device scratch --------
__device__ __align__(16) float g_h[NN*DD];
__device__ __align__(16) float g_h1[NN];
__device__ __align__(16) float g_h2[NN];
__device__ __align__(16) __nv_bfloat16 g_ht_hi[(size_t)DD*NN];
__device__ __align__(16) __nv_bfloat16 g_ht_lo[(size_t)DD*NN];
__device__ __align__(16) float g_acc[(size_t)JS*NN*DD];
__device__ __align__(16) float g_Z[JS*NN];

// -------- helpers --------
__device__ __forceinline__ uint32_t s2u(const void* p) {
    uint32_t a;
    asm("{ .reg .u64 t; cvta.to.shared.u64 t, %1; cvt.u32.u64 %0, t; }" : "=r"(a) : "l"(p));
    return a;
}
#define CPA16(dst, src) asm volatile("cp.async.cg.shared.global [%0], [%1], 16;" :: "r"(dst), "l"(src))
#define CPCOMMIT()      asm volatile("cp.async.commit_group;" ::: "memory")
#define CPWAIT0()       asm volatile("cp.async.wait_group 0;" ::: "memory")
#define CPWAIT1()       asm volatile("cp.async.wait_group 1;" ::: "memory")
#define LDM4(r, a) \
    asm volatile("ldmatrix.sync.aligned.m8n8.x4.shared.b16 {%0,%1,%2,%3},[%4];" \
        : "=r"((r)[0]), "=r"((r)[1]), "=r"((r)[2]), "=r"((r)[3]) : "r"(a))
#define MMA(d, a, b0, b1) \
    asm volatile("mma.sync.aligned.m16n8k16.row.col.f32.bf16.bf16.f32 " \
        "{%0,%1,%2,%3},{%4,%5,%6,%7},{%8,%9},{%0,%1,%2,%3};" \
        : "+f"((d)[0]), "+f"((d)[1]), "+f"((d)[2]), "+f"((d)[3]) \
        : "r"((a)[0]), "r"((a)[1]), "r"((a)[2]), "r"((a)[3]), "r"(b0), "r"(b1))

// ---------------- kernel 1: h = X @ W ----------------
__global__ void __launch_bounds__(256) gemm_h_kernel(const float* __restrict__ X,
                                                     const float* __restrict__ W) {
    __shared__ float xs[16][IND];
    const int tid = threadIdx.x;
    const int row0 = blockIdx.x * 16;
    {
        const float4* src = (const float4*)(X + (size_t)row0 * IND);
        float4* dst = (float4*)&xs[0][0];
        #pragma unroll
        for (int i = 0; i < 8; i++) dst[tid + i*256] = src[tid + i*256];
    }
    __syncthreads();
    const int c  = tid & 63;
    const int rg = tid >> 6;
    float a0 = 0.f, a1 = 0.f, a2 = 0.f, a3 = 0.f;
    #pragma unroll 4
    for (int k = 0; k < IND; k++) {
        const float w = W[k*DD + c];
        a0 += xs[rg*4+0][k] * w;
        a1 += xs[rg*4+1][k] * w;
        a2 += xs[rg*4+2][k] * w;
        a3 += xs[rg*4+3][k] * w;
    }
    g_h[(row0 + rg*4+0)*DD + c] = a0;
    g_h[(row0 + rg*4+1)*DD + c] = a1;
    g_h[(row0 + rg*4+2)*DD + c] = a2;
    g_h[(row0 + rg*4+3)*DD + c] = a3;
}

// ---------------- kernel 2: transpose h -> ht_hi/ht_lo ----------------
__global__ void __launch_bounds__(256) ht_kernel() {
    __shared__ float ts[64][65];
    const int tid = threadIdx.x;
    const int j0 = blockIdx.x * 64;
    #pragma unroll
    for (int k = 0; k < 16; ++k) {
        int e = k*256 + tid;
        ts[e>>6][e&63] = g_h[(j0 + (e>>6))*DD + (e&63)];
    }
    __syncthreads();
    #pragma unroll
    for (int k = 0; k < 16; ++k) {
        int e = k*256 + tid;
        int c = e >> 6, jj = e & 63;
        float v = ts[jj][c];
        __nv_bfloat16 hb = __float2bfloat16(v);
        g_ht_hi[(size_t)c*NN + j0 + jj] = hb;
        g_ht_lo[(size_t)c*NN + j0 + jj] = __float2bfloat16(v - __bfloat162float(hb));
    }
}

// ---------------- kernel 3: h1 / h2 projections ----------------
__global__ void __launch_bounds__(256) proj_kernel(const float* __restrict__ a) {
    const int w = threadIdx.x >> 5, lane = threadIdx.x & 31;
    const int row = blockIdx.x * 8 + w;
    const float x0 = g_h[row*DD + lane];
    const float x1 = g_h[row*DD + 32 + lane];
    float s1 = x0 * a[lane]      + x1 * a[lane + 32];
    float s2 = x0 * a[64 + lane] + x1 * a[96 + lane];
    #pragma unroll
    for (int o = 16; o > 0; o >>= 1) {
        s1 += __shfl_xor_sync(0xffffffffu, s1, o);
        s2 += __shfl_xor_sync(0xffffffffu, s2, o);
    }
    if (lane == 0) { g_h1[row] = s1; g_h2[row] = s2; }
}

// ---------------- kernel 4: fused attention, phase-interleaved pipeline ----------------
__device__ __forceinline__ float pexp(int a, float e) {
    const float s = fmaxf(e, ALPHA * e);
    const float p = __expf(s);
    return (a > 0) ? p : 0.f;
}
__device__ __forceinline__ uint32_t pack_hilo(float x, float y, uint32_t& lo) {
    __nv_bfloat162 H = __float22bfloat162_rn(make_float2(x, y));
    float2 f = __bfloat1622float2(H);
    __nv_bfloat162 L = __float22bfloat162_rn(make_float2(x - f.x, y - f.y));
    lo = *reinterpret_cast<uint32_t*>(&L);
    return *reinterpret_cast<uint32_t*>(&H);
}

// load adj + h2 chunk kb of tile at jn into pa/ph
#define LDGX_KB(kb, jn) do { \
    const int jb = (jn) + (kb) * 16 + jq; \
    pa[kb][0] = __ldcs((const int2*)(adjA + jb)); \
    pa[kb][1] = __ldcs((const int2*)(adjB + jb)); \
    pa[kb][2] = __ldcs((const int2*)(adjA + jb + 8)); \
    pa[kb][3] = __ldcs((const int2*)(adjB + jb + 8)); \
    ph0[kb] = *(const float2*)(g_h2 + jb); \
    ph1[kb] = *(const float2*)(g_h2 + jb + 8); \
} while(0)

// P-gen chunk kb: pa/ph -> NHI/NLO fragments + z
#define PGEN_KB(kb, NHI, NLO) do { \
    const float p00 = pexp(pa[kb][0].x, h1a + ph0[kb].x), p01 = pexp(pa[kb][0].y, h1a + ph0[kb].y); \
    const float p10 = pexp(pa[kb][1].x, h1b + ph0[kb].x), p11 = pexp(pa[kb][1].y, h1b + ph0[kb].y); \
    const float p02 = pexp(pa[kb][2].x, h1a + ph1[kb].x), p03 = pexp(pa[kb][2].y, h1a + ph1[kb].y); \
    const float p12 = pexp(pa[kb][3].x, h1b + ph1[kb].x), p13 = pexp(pa[kb][3].y, h1b + ph1[kb].y); \
    z0 += (p00 + p01) + (p02 + p03); \
    z1 += (p10 + p11) + (p12 + p13); \
    NHI[kb][0] = pack_hilo(p00, p01, NLO[kb][0]); \
    NHI[kb][1] = pack_hilo(p10, p11, NLO[kb][1]); \
    NHI[kb][2] = pack_hilo(p02, p03, NLO[kb][2]); \
    NHI[kb][3] = pack_hilo(p12, p13, NLO[kb][3]); \
} while(0)

// one n-block of MMAs for the current tile
#define MMA_NB(nb, curb, AHI, ALO) do { \
    const uint32_t rowa = (curb) + (uint32_t)(((nb) * 8 + lmr) * 64 + (lmx * 8)) * 2; \
    uint32_t bh[8], bl[8]; \
    LDM4(bh, rowa); LDM4(bh + 4, rowa ^ 64u); \
    LDM4(bl, rowa + PL); LDM4(bl + 4, (rowa + PL) ^ 64u); \
    _Pragma("unroll") \
    for (int kb = 0; kb < 4; kb++) { \
        MMA(acc[nb], AHI[kb], bh[2*kb], bh[2*kb+1]); \
        MMA(acc[nb], ALO[kb], bh[2*kb], bh[2*kb+1]); \
        MMA(acc[nb], AHI[kb], bl[2*kb], bl[2*kb+1]); \
    } \
} while(0)

// stage H tile (hi+lo) at column-offset jn into buffer offset bufoff
#define STAGE_H(bufoff, jn) do { \
    _Pragma("unroll") \
    for (int q = 0; q < 4; q++) { \
        const int idx = tid + q * 128; \
        const int cc = idx >> 3, seg = idx & 7; \
        const uint32_t dst = smem0 + (bufoff) + (uint32_t)(cc * 64 + ((seg ^ (cc & 7)) * 8)) * 2; \
        const size_t off = (size_t)cc * NN + (jn) + seg * 8; \
        CPA16(dst, g_ht_hi + off); \
        CPA16(dst + PL, g_ht_lo + off); \
    } \
} while(0)

// pipelined iteration: MMA(t) + P-gen(t+1) + LDG(t+2) interleaved, then stage H(t+2)
#define PIPE_ITER(t, AHI, ALO, NHI, NLO) do { \
    CPWAIT1(); __syncthreads(); \
    const uint32_t curb = smem0 + (uint32_t)((t) & 1) * BUFB; \
    const int tn = ((t) + 2 < NTILES) ? (t) + 2 : NTILES - 1; \
    const int jn2 = jbase + tn * KT; \
    _Pragma("unroll") \
    for (int nb = 0; nb < 8; nb++) { \
        MMA_NB(nb, curb, AHI, ALO); \
        if (nb < 4) PGEN_KB(nb, NHI, NLO); \
        if (nb >= 1 && nb < 5) LDGX_KB(nb - 1, jn2); \
    } \
    __syncthreads(); \
    STAGE_H((uint32_t)((t) & 1) * BUFB, jn2); \
    CPCOMMIT(); \
} while(0)

// 128 threads (4 warps), 64 rows per CTA. grid (JS, NN/64). 2 CTAs/SM.
__global__ void __launch_bounds__(128, 2) attn_kernel(const int* __restrict__ adj) {
    __shared__ __nv_bfloat16 hts[2][2][64][64];   // 32 KB

    const int tid = threadIdx.x, lane = tid & 31, w = tid >> 5;
    const int jsb = blockIdx.x;
    const int row0 = blockIdx.y * 64;
    const int jbase = jsb * JLEN;
    const int g  = row0 + w * 16 + (lane >> 2);
    const int jq = (lane & 3) * 2;

    const float h1a = g_h1[g];
    const float h1b = g_h1[g + 8];
    const int* adjA = adj + (size_t)g * NN;
    const int* adjB = adj + (size_t)(g + 8) * NN;

    const int lmr = lane & 7;
    const int lmx = (lane >> 3) ^ lmr;
    const uint32_t smem0 = s2u(&hts[0][0][0][0]);
    const uint32_t PL   = 64 * 64 * 2;
    const uint32_t BUFB = 2 * PL;

    float acc[8][4];
    #pragma unroll
    for (int nb = 0; nb < 8; nb++) { acc[nb][0]=acc[nb][1]=acc[nb][2]=acc[nb][3]=0.f; }
    float z0 = 0.f, z1 = 0.f;

    int2 pa[4][4];
    float2 ph0[4], ph1[4];
    uint32_t ahiA[4][4], aloA[4][4], ahiB[4][4], aloB[4][4];

    // ---- prologue: P(0) into A; adj(1) into pa; H(0),H(1) staged ----
    #pragma unroll
    for (int kb = 0; kb < 4; kb++) LDGX_KB(kb, jbase);
    #pragma unroll
    for (int kb = 0; kb < 4; kb++) PGEN_KB(kb, ahiA, aloA);
    #pragma unroll
    for (int kb = 0; kb < 4; kb++) LDGX_KB(kb, jbase + KT);
    STAGE_H(0u, jbase);
    CPCOMMIT();
    STAGE_H(BUFB, jbase + KT);
    CPCOMMIT();

    // ---- main pipelined loop: iterations t = 0..30 ----
    #pragma unroll 1
    for (int t = 0; t < NTILES - 2; t += 2) {
        PIPE_ITER(t,     ahiA, aloA, ahiB, aloB);
        PIPE_ITER(t + 1, ahiB, aloB, ahiA, aloA);
    }
    PIPE_ITER(NTILES - 2, ahiA, aloA, ahiB, aloB);   // t = 30, produces P(31) in B

    // ---- epilogue: MMA tile 31 ----
    CPWAIT0();
    __syncthreads();
    {
        const uint32_t curb = smem0 + (uint32_t)((NTILES - 1) & 1) * BUFB;
        #pragma unroll
        for (int nb = 0; nb < 8; nb++) MMA_NB(nb, curb, ahiB, aloB);
    }

    // ---- Z reduce across 4 lanes sharing a row ----
    z0 += __shfl_xor_sync(0xffffffffu, z0, 1);
    z0 += __shfl_xor_sync(0xffffffffu, z0, 2);
    z1 += __shfl_xor_sync(0xffffffffu, z1, 1);
    z1 += __shfl_xor_sync(0xffffffffu, z1, 2);
    if ((lane & 3) == 0) {
        g_Z[jsb*NN + g]     = z0;
        g_Z[jsb*NN + g + 8] = z1;
    }

    // ---- partial numerators ----
    #pragma unroll
    for (int nb = 0; nb < 8; nb++) {
        float2 v0; v0.x = acc[nb][0]; v0.y = acc[nb][1];
        float2 v1; v1.x = acc[nb][2]; v1.y = acc[nb][3];
        *(float2*)&g_acc[((size_t)jsb*NN + g    )*DD + nb*8 + jq] = v0;
        *(float2*)&g_acc[((size_t)jsb*NN + g + 8)*DD + nb*8 + jq] = v1;
    }
}

// ---------------- kernel 5: combine splits, normalize, ELU ----------------
__global__ void __launch_bounds__(256) combine_kernel(float* __restrict__ out) {
    const int gid = blockIdx.x * 256 + threadIdx.x;
    const int i = gid >> 6;
    float s = 0.f, z = 0.f;
    #pragma unroll
    for (int q = 0; q < JS; q++) {
        s += g_acc[(size_t)q*NN*DD + gid];
        z += g_Z[q*NN + i];
    }
    const float o = s / z;
    out[gid] = (o > 0.f) ? o : expm1f(o);
}

// ---------------- launcher ----------------
extern "C" void kernel_launch(void* const* d_in, const int* in_sizes, int n_in,
                              void* d_out, int out_size) {
    const float* features = (const float*)d_in[0];
    const int*   adj      = (const int*)d_in[1];
    const float* W        = (const float*)d_in[2];
    const float* a        = (const float*)d_in[3];
    float* out = (float*)d_out;

    gemm_h_kernel<<<NN/16, 256>>>(features, W);
    ht_kernel<<<NN/64, 256>>>();
    proj_kernel<<<NN/8, 256>>>(a);
    attn_kernel<<<dim3(JS, NN/64), 128>>>(adj);
    combine_kernel<<<(NN*DD)/256, 256>>>(out);
}